// round 1
// baseline (speedup 1.0000x reference)
#include <cuda_runtime.h>
#include <math.h>

#define Bx 4
#define Nx 2048
#define DIMx 256
#define Hx 8
#define HDx 32
#define Fx 64            // 2*HD feature dim (cos|sin)
#define MTOT (Bx*Nx)     // 8192

#define BM 64
#define BN 64
#define QSTR 68          // padded stride for transposed Q/K smem tiles

// scratch (allocation-free rule: __device__ globals)
__device__ float g_Qf[Bx*Hx*Nx*Fx];     // [bh][n][64]  (cos|sin)
__device__ float g_Kf[Bx*Hx*Nx*Fx];
__device__ float g_V [Bx*Hx*Nx*HDx];    // [bh][n][32]
__device__ float g_AO[MTOT*DIMx];       // attention output, [row][dim]

// ---------------------------------------------------------------------------
// Kernel 1: QKV projection + feature map epilogue.
// C[8192,256] = X @ W + b; blockIdx.z selects Q/K/V.
// 64x64 tile, 256 threads, 4x4 per thread, BK=16.
// ---------------------------------------------------------------------------
__global__ __launch_bounds__(256)
void qkv_kernel(const float* __restrict__ x,
                const float* __restrict__ Wq, const float* __restrict__ bq,
                const float* __restrict__ Wk, const float* __restrict__ bk,
                const float* __restrict__ Wv, const float* __restrict__ bv)
{
    const int mode = blockIdx.z;
    const float* W    = (mode == 0) ? Wq : (mode == 1) ? Wk : Wv;
    const float* bias = (mode == 0) ? bq : (mode == 1) ? bk : bv;

    __shared__ float As[16][65];   // [k][m]
    __shared__ float Bs[16][64];   // [k][n]

    const int t  = threadIdx.x;
    const int ty = t >> 4, tx = t & 15;
    const int rowBase = blockIdx.y * 64;
    const int colBase = blockIdx.x * 64;

    float c[4][4] = {};

    for (int k0 = 0; k0 < DIMx; k0 += 16) {
        // load A tile (transpose)
        {
            int ar = t >> 2;
            int ak = (t & 3) * 4;
            float4 av = *(const float4*)&x[(size_t)(rowBase + ar) * DIMx + k0 + ak];
            As[ak + 0][ar] = av.x; As[ak + 1][ar] = av.y;
            As[ak + 2][ar] = av.z; As[ak + 3][ar] = av.w;
            int bkk = t >> 4;
            int bn  = (t & 15) * 4;
            *(float4*)&Bs[bkk][bn] = *(const float4*)&W[(size_t)(k0 + bkk) * DIMx + colBase + bn];
        }
        __syncthreads();
        #pragma unroll
        for (int k = 0; k < 16; k++) {
            float a0 = As[k][ty * 4 + 0], a1 = As[k][ty * 4 + 1];
            float a2 = As[k][ty * 4 + 2], a3 = As[k][ty * 4 + 3];
            float4 b4 = *(const float4*)&Bs[k][tx * 4];
            c[0][0] += a0 * b4.x; c[0][1] += a0 * b4.y; c[0][2] += a0 * b4.z; c[0][3] += a0 * b4.w;
            c[1][0] += a1 * b4.x; c[1][1] += a1 * b4.y; c[1][2] += a1 * b4.z; c[1][3] += a1 * b4.w;
            c[2][0] += a2 * b4.x; c[2][1] += a2 * b4.y; c[2][2] += a2 * b4.z; c[2][3] += a2 * b4.w;
            c[3][0] += a3 * b4.x; c[3][1] += a3 * b4.y; c[3][2] += a3 * b4.z; c[3][3] += a3 * b4.w;
        }
        __syncthreads();
    }

    float* dstF = (mode == 0) ? g_Qf : g_Kf;
    #pragma unroll
    for (int i = 0; i < 4; i++) {
        int row = rowBase + ty * 4 + i;
        int b   = row >> 11;          // N = 2048
        int n   = row & (Nx - 1);
        #pragma unroll
        for (int j = 0; j < 4; j++) {
            int col = colBase + tx * 4 + j;
            float val = c[i][j] + bias[col];
            int h = col >> 5, d = col & 31;
            if (mode == 2) {
                g_V[((size_t)(b * Hx + h) * Nx + n) * HDx + d] = val;
            } else {
                float sn, cn;
                sincosf(val, &sn, &cn);
                size_t base = ((size_t)(b * Hx + h) * Nx + n) * Fx;
                dstF[base + d]      = cn;
                dstF[base + 32 + d] = sn;
            }
        }
    }
}

// ---------------------------------------------------------------------------
// Kernel 2: flash attention with topo-weighted scores.
// grid (N/64, H, B), 256 threads, dynamic smem.
// ---------------------------------------------------------------------------
__global__ __launch_bounds__(256)
void attn_kernel(const float* __restrict__ topo)
{
    extern __shared__ float smem[];
    float* Qs = smem;                 // [f*QSTR + m], 64x68
    float* Ks = Qs + 64 * QSTR;       // [f*QSTR + m], 64x68
    float* Vs = Ks + 64 * QSTR;       // [m*33 + d],   64x33
    float* TP = Vs + 64 * 33;         // [r*64 + c],   topo tile then P tile

    const int t  = threadIdx.x;
    const int ty = t >> 4, tx = t & 15;
    const int n0 = blockIdx.x * BM;
    const int h  = blockIdx.y;
    const int b  = blockIdx.z;
    const int bh = b * Hx + h;

    const float* Qg = g_Qf + (size_t)bh * Nx * Fx;
    const float* Kg = g_Kf + (size_t)bh * Nx * Fx;
    const float* Vg = g_V  + (size_t)bh * Nx * HDx;
    const float* Tg = topo + (size_t)b * Nx * Nx;

    const float SCALE = 0.35355339059327373f;  // 2/sqrt(32)

    // load Q tile transposed: Qs[f][m]
    {
        int r  = t >> 2;
        int c0 = (t & 3) * 4;
        #pragma unroll
        for (int j = 0; j < 4; j++) {
            int f = c0 + j * 16;
            float4 v = *(const float4*)&Qg[(size_t)(n0 + r) * Fx + f];
            Qs[(f + 0) * QSTR + r] = v.x;
            Qs[(f + 1) * QSTR + r] = v.y;
            Qs[(f + 2) * QSTR + r] = v.z;
            Qs[(f + 3) * QSTR + r] = v.w;
        }
    }

    float m_run[4] = {-INFINITY, -INFINITY, -INFINITY, -INFINITY};
    float l_run[4] = {0.f, 0.f, 0.f, 0.f};
    float acc[4][2] = {};

    for (int kt = 0; kt < Nx / BN; kt++) {
        const int m0 = kt * BN;
        // load K tile transposed
        {
            int r  = t >> 2;
            int c0 = (t & 3) * 4;
            #pragma unroll
            for (int j = 0; j < 4; j++) {
                int f = c0 + j * 16;
                float4 v = *(const float4*)&Kg[(size_t)(m0 + r) * Fx + f];
                Ks[(f + 0) * QSTR + r] = v.x;
                Ks[(f + 1) * QSTR + r] = v.y;
                Ks[(f + 2) * QSTR + r] = v.z;
                Ks[(f + 3) * QSTR + r] = v.w;
            }
        }
        // load V tile [m][d]
        #pragma unroll
        for (int u = 0; u < 2; u++) {
            int id = t + u * 256;          // 0..511 float4s
            int r = id >> 3, c = (id & 7) * 4;
            float4 v = *(const float4*)&Vg[(size_t)(m0 + r) * HDx + c];
            Vs[r * 33 + c + 0] = v.x; Vs[r * 33 + c + 1] = v.y;
            Vs[r * 33 + c + 2] = v.z; Vs[r * 33 + c + 3] = v.w;
        }
        // load topo tile [r][c]
        {
            int r  = t >> 2;
            int c0 = (t & 3) * 4;
            #pragma unroll
            for (int j = 0; j < 4; j++) {
                int c = c0 + j * 16;
                *(float4*)&TP[r * 64 + c] =
                    *(const float4*)&Tg[(size_t)(n0 + r) * Nx + m0 + c];
            }
        }
        __syncthreads();

        // S = Q @ K^T
        float s[4][4] = {};
        #pragma unroll 16
        for (int f = 0; f < Fx; f++) {
            float4 a  = *(const float4*)&Qs[f * QSTR + ty * 4];
            float4 b4 = *(const float4*)&Ks[f * QSTR + tx * 4];
            s[0][0] += a.x * b4.x; s[0][1] += a.x * b4.y; s[0][2] += a.x * b4.z; s[0][3] += a.x * b4.w;
            s[1][0] += a.y * b4.x; s[1][1] += a.y * b4.y; s[1][2] += a.y * b4.z; s[1][3] += a.y * b4.w;
            s[2][0] += a.z * b4.x; s[2][1] += a.z * b4.y; s[2][2] += a.z * b4.z; s[2][3] += a.z * b4.w;
            s[3][0] += a.w * b4.x; s[3][1] += a.w * b4.y; s[3][2] += a.w * b4.z; s[3][3] += a.w * b4.w;
        }

        // scale by 2/sqrt(HD) * topo
        #pragma unroll
        for (int i = 0; i < 4; i++)
            #pragma unroll
            for (int j = 0; j < 4; j++)
                s[i][j] *= SCALE * TP[(ty * 4 + i) * 64 + tx * 4 + j];

        // online softmax (row reductions across the 16 tx lanes)
        #pragma unroll
        for (int i = 0; i < 4; i++) {
            float tm = fmaxf(fmaxf(s[i][0], s[i][1]), fmaxf(s[i][2], s[i][3]));
            #pragma unroll
            for (int off = 8; off >= 1; off >>= 1)
                tm = fmaxf(tm, __shfl_xor_sync(0xffffffffu, tm, off, 16));
            float mn   = fmaxf(m_run[i], tm);
            float corr = __expf(m_run[i] - mn);
            m_run[i] = mn;
            float rs = 0.f;
            #pragma unroll
            for (int j = 0; j < 4; j++) {
                s[i][j] = __expf(s[i][j] - mn);
                rs += s[i][j];
            }
            #pragma unroll
            for (int off = 8; off >= 1; off >>= 1)
                rs += __shfl_xor_sync(0xffffffffu, rs, off, 16);
            l_run[i] = l_run[i] * corr + rs;
            acc[i][0] *= corr;
            acc[i][1] *= corr;
            // each thread overwrites only its own 4x4 topo slots -> no sync needed
            #pragma unroll
            for (int j = 0; j < 4; j++)
                TP[(ty * 4 + i) * 64 + tx * 4 + j] = s[i][j];
        }
        __syncthreads();

        // acc += P @ V (thread cols = tx*2, tx*2+1)
        #pragma unroll 8
        for (int k = 0; k < BN; k++) {
            float v0 = Vs[k * 33 + tx * 2 + 0];
            float v1 = Vs[k * 33 + tx * 2 + 1];
            #pragma unroll
            for (int i = 0; i < 4; i++) {
                float p = TP[(ty * 4 + i) * 64 + k];
                acc[i][0] += p * v0;
                acc[i][1] += p * v1;
            }
        }
        __syncthreads();
    }

    #pragma unroll
    for (int i = 0; i < 4; i++) {
        float inv = 1.0f / l_run[i];
        int row = n0 + ty * 4 + i;
        size_t base = ((size_t)(b * Nx + row)) * DIMx + h * HDx + tx * 2;
        g_AO[base + 0] = acc[i][0] * inv;
        g_AO[base + 1] = acc[i][1] * inv;
    }
}

// ---------------------------------------------------------------------------
// Kernel 3: output projection  out = AO @ Wo + bo
// ---------------------------------------------------------------------------
__global__ __launch_bounds__(256)
void proj_kernel(const float* __restrict__ Wo, const float* __restrict__ bo,
                 float* __restrict__ out)
{
    __shared__ float As[16][65];
    __shared__ float Bs[16][64];

    const int t  = threadIdx.x;
    const int ty = t >> 4, tx = t & 15;
    const int rowBase = blockIdx.y * 64;
    const int colBase = blockIdx.x * 64;

    float c[4][4] = {};

    for (int k0 = 0; k0 < DIMx; k0 += 16) {
        {
            int ar = t >> 2;
            int ak = (t & 3) * 4;
            float4 av = *(const float4*)&g_AO[(size_t)(rowBase + ar) * DIMx + k0 + ak];
            As[ak + 0][ar] = av.x; As[ak + 1][ar] = av.y;
            As[ak + 2][ar] = av.z; As[ak + 3][ar] = av.w;
            int bkk = t >> 4;
            int bn  = (t & 15) * 4;
            *(float4*)&Bs[bkk][bn] = *(const float4*)&Wo[(size_t)(k0 + bkk) * DIMx + colBase + bn];
        }
        __syncthreads();
        #pragma unroll
        for (int k = 0; k < 16; k++) {
            float a0 = As[k][ty * 4 + 0], a1 = As[k][ty * 4 + 1];
            float a2 = As[k][ty * 4 + 2], a3 = As[k][ty * 4 + 3];
            float4 b4 = *(const float4*)&Bs[k][tx * 4];
            c[0][0] += a0 * b4.x; c[0][1] += a0 * b4.y; c[0][2] += a0 * b4.z; c[0][3] += a0 * b4.w;
            c[1][0] += a1 * b4.x; c[1][1] += a1 * b4.y; c[1][2] += a1 * b4.z; c[1][3] += a1 * b4.w;
            c[2][0] += a2 * b4.x; c[2][1] += a2 * b4.y; c[2][2] += a2 * b4.z; c[2][3] += a2 * b4.w;
            c[3][0] += a3 * b4.x; c[3][1] += a3 * b4.y; c[3][2] += a3 * b4.z; c[3][3] += a3 * b4.w;
        }
        __syncthreads();
    }

    #pragma unroll
    for (int i = 0; i < 4; i++) {
        int row = rowBase + ty * 4 + i;
        #pragma unroll
        for (int j = 0; j < 4; j++) {
            int col = colBase + tx * 4 + j;
            out[(size_t)row * DIMx + col] = c[i][j] + bo[col];
        }
    }
}

// ---------------------------------------------------------------------------

static const int ATTN_SMEM_BYTES = (64 * QSTR + 64 * QSTR + 64 * 33 + 64 * 64) * 4; // 59648

extern "C" void kernel_launch(void* const* d_in, const int* in_sizes, int n_in,
                              void* d_out, int out_size)
{
    const float* x    = (const float*)d_in[0];
    const float* topo = (const float*)d_in[1];
    const float* Wq   = (const float*)d_in[2];
    const float* bq   = (const float*)d_in[3];
    const float* Wk   = (const float*)d_in[4];
    const float* bk   = (const float*)d_in[5];
    const float* Wv   = (const float*)d_in[6];
    const float* bv   = (const float*)d_in[7];
    const float* Wo   = (const float*)d_in[8];
    const float* bo   = (const float*)d_in[9];
    float* out = (float*)d_out;
    (void)in_sizes; (void)n_in; (void)out_size;

    cudaFuncSetAttribute(attn_kernel,
                         cudaFuncAttributeMaxDynamicSharedMemorySize,
                         ATTN_SMEM_BYTES);

    dim3 gq(DIMx / 64, MTOT / 64, 3);
    qkv_kernel<<<gq, 256>>>(x, Wq, bq, Wk, bk, Wv, bv);

    dim3 ga(Nx / BM, Hx, Bx);
    attn_kernel<<<ga, 256, ATTN_SMEM_BYTES>>>(topo);

    dim3 go(DIMx / 64, MTOT / 64);
    proj_kernel<<<go, 256>>>(Wo, bo, out);
}

// round 3
// speedup vs baseline: 2.1706x; 2.1706x over previous
#include <cuda_runtime.h>
#include <cuda_bf16.h>
#include <math.h>
#include <stdint.h>

#define Bx 4
#define Nx 2048
#define DIMx 256
#define Hx 8
#define HDx 32
#define Fx 64
#define MTOT (Bx*Nx)

// ------------------------- device scratch (no allocs) -----------------------
__device__ __nv_bfloat16 g_Qhi[Bx*Hx*Nx*Fx];
__device__ __nv_bfloat16 g_Qlo[Bx*Hx*Nx*Fx];
__device__ __nv_bfloat16 g_Khi[Bx*Hx*Nx*Fx];
__device__ __nv_bfloat16 g_Klo[Bx*Hx*Nx*Fx];
__device__ __nv_bfloat16 g_Vthi[Bx*Hx*HDx*Nx];   // [bh][d][n] transposed
__device__ __nv_bfloat16 g_Vtlo[Bx*Hx*HDx*Nx];
__device__ float g_AO[MTOT*DIMx];

// ------------------------- helpers ------------------------------------------
__device__ __forceinline__ uint32_t smem_u32(const void* p) {
    uint32_t a;
    asm("{ .reg .u64 t; cvta.to.shared.u64 t, %1; cvt.u32.u64 %0, t; }" : "=r"(a) : "l"(p));
    return a;
}
__device__ __forceinline__ uint32_t packbf2(float lo, float hi) {
    uint32_t r;
    asm("cvt.rn.bf16x2.f32 %0, %1, %2;" : "=r"(r) : "f"(hi), "f"(lo));
    return r;   // lo -> bits[15:0], hi -> bits[31:16]
}
__device__ __forceinline__ void ldsm4(uint32_t* r, uint32_t addr) {
    asm volatile("ldmatrix.sync.aligned.m8n8.x4.shared.b16 {%0,%1,%2,%3}, [%4];"
        : "=r"(r[0]), "=r"(r[1]), "=r"(r[2]), "=r"(r[3]) : "r"(addr));
}
__device__ __forceinline__ void mma_bf16(float* c, const uint32_t* a, const uint32_t* b) {
    asm volatile("mma.sync.aligned.m16n8k16.row.col.f32.bf16.bf16.f32 "
        "{%0,%1,%2,%3}, {%4,%5,%6,%7}, {%8,%9}, {%0,%1,%2,%3};"
        : "+f"(c[0]), "+f"(c[1]), "+f"(c[2]), "+f"(c[3])
        : "r"(a[0]), "r"(a[1]), "r"(a[2]), "r"(a[3]), "r"(b[0]), "r"(b[1]));
}
__device__ __forceinline__ uint32_t sw128(uint32_t off) {
    return off ^ ((off >> 3) & 0x70);
}

// ---------------------------------------------------------------------------
// Kernel 1: QKV projection + feature-map + bf16 hi/lo split epilogue
// ---------------------------------------------------------------------------
__global__ __launch_bounds__(256)
void qkv_kernel(const float* __restrict__ x,
                const float* __restrict__ Wq, const float* __restrict__ bq,
                const float* __restrict__ Wk, const float* __restrict__ bk,
                const float* __restrict__ Wv, const float* __restrict__ bv)
{
    const int mode = blockIdx.z;
    const float* W    = (mode == 0) ? Wq : (mode == 1) ? Wk : Wv;
    const float* bias = (mode == 0) ? bq : (mode == 1) ? bk : bv;

    __shared__ float As[16][65];
    __shared__ float Bs[16][64];

    const int t  = threadIdx.x;
    const int ty = t >> 4, tx = t & 15;
    const int rowBase = blockIdx.y * 64;
    const int colBase = blockIdx.x * 64;

    float c[4][4] = {};

    for (int k0 = 0; k0 < DIMx; k0 += 16) {
        {
            int ar = t >> 2;
            int ak = (t & 3) * 4;
            float4 av = *(const float4*)&x[(size_t)(rowBase + ar) * DIMx + k0 + ak];
            As[ak + 0][ar] = av.x; As[ak + 1][ar] = av.y;
            As[ak + 2][ar] = av.z; As[ak + 3][ar] = av.w;
            int bkk = t >> 4;
            int bn  = (t & 15) * 4;
            *(float4*)&Bs[bkk][bn] = *(const float4*)&W[(size_t)(k0 + bkk) * DIMx + colBase + bn];
        }
        __syncthreads();
        #pragma unroll
        for (int k = 0; k < 16; k++) {
            float a0 = As[k][ty*4+0], a1 = As[k][ty*4+1];
            float a2 = As[k][ty*4+2], a3 = As[k][ty*4+3];
            float4 b4 = *(const float4*)&Bs[k][tx*4];
            c[0][0] += a0*b4.x; c[0][1] += a0*b4.y; c[0][2] += a0*b4.z; c[0][3] += a0*b4.w;
            c[1][0] += a1*b4.x; c[1][1] += a1*b4.y; c[1][2] += a1*b4.z; c[1][3] += a1*b4.w;
            c[2][0] += a2*b4.x; c[2][1] += a2*b4.y; c[2][2] += a2*b4.z; c[2][3] += a2*b4.w;
            c[3][0] += a3*b4.x; c[3][1] += a3*b4.y; c[3][2] += a3*b4.z; c[3][3] += a3*b4.w;
        }
        __syncthreads();
    }

    const int col0 = colBase + tx * 4;
    const int h  = col0 >> 5;
    const int d0 = col0 & 31;

    if (mode == 2) {
        const int rowb = rowBase + ty * 4;
        const int bb = rowb >> 11;
        const int n00 = rowb & (Nx - 1);
        #pragma unroll
        for (int j = 0; j < 4; j++) {
            float v0 = c[0][j] + bias[col0 + j];
            float v1 = c[1][j] + bias[col0 + j];
            float v2 = c[2][j] + bias[col0 + j];
            float v3 = c[3][j] + bias[col0 + j];
            uint32_t h01 = packbf2(v0, v1), h23 = packbf2(v2, v3);
            float hf0 = __uint_as_float(h01 << 16), hf1 = __uint_as_float(h01 & 0xffff0000u);
            float hf2 = __uint_as_float(h23 << 16), hf3 = __uint_as_float(h23 & 0xffff0000u);
            uint32_t l01 = packbf2(v0 - hf0, v1 - hf1), l23 = packbf2(v2 - hf2, v3 - hf3);
            size_t base = ((size_t)((bb*Hx + h)*HDx + d0 + j)) * Nx + n00;
            *(uint32_t*)&g_Vthi[base]     = h01;
            *(uint32_t*)&g_Vthi[base + 2] = h23;
            *(uint32_t*)&g_Vtlo[base]     = l01;
            *(uint32_t*)&g_Vtlo[base + 2] = l23;
        }
    } else {
        __nv_bfloat16* dhi = (mode == 0) ? g_Qhi : g_Khi;
        __nv_bfloat16* dlo = (mode == 0) ? g_Qlo : g_Klo;
        #pragma unroll
        for (int i = 0; i < 4; i++) {
            int row = rowBase + ty*4 + i;
            int bb = row >> 11;
            int n  = row & (Nx - 1);
            float cn[4], sn[4];
            #pragma unroll
            for (int j = 0; j < 4; j++) {
                float val = c[i][j] + bias[col0 + j];
                sincosf(val, &sn[j], &cn[j]);
            }
            size_t fb = ((size_t)(bb*Hx + h) * Nx + n) * Fx;
            #pragma unroll
            for (int jp = 0; jp < 2; jp++) {
                float a = cn[2*jp], b2 = cn[2*jp+1];
                uint32_t hp = packbf2(a, b2);
                float ha = __uint_as_float(hp << 16), hb = __uint_as_float(hp & 0xffff0000u);
                uint32_t lp = packbf2(a - ha, b2 - hb);
                *(uint32_t*)&dhi[fb + d0 + 2*jp] = hp;
                *(uint32_t*)&dlo[fb + d0 + 2*jp] = lp;
                a = sn[2*jp]; b2 = sn[2*jp+1];
                hp = packbf2(a, b2);
                ha = __uint_as_float(hp << 16); hb = __uint_as_float(hp & 0xffff0000u);
                lp = packbf2(a - ha, b2 - hb);
                *(uint32_t*)&dhi[fb + 32 + d0 + 2*jp] = hp;
                *(uint32_t*)&dlo[fb + 32 + d0 + 2*jp] = lp;
            }
        }
    }
}

// ---------------------------------------------------------------------------
// Kernel 2: mma.sync flash attention (split-bf16, fixed-max softmax)
// 128 threads / 4 warps; Q tile 64 (16 rows per warp); KV tile 64; 32 iters
// ---------------------------------------------------------------------------
#define SCALEC 0.35355339059327373f
#define SMAXC  11.4f

// smem offsets (bytes)
#define SQHI 0u
#define SQLO 8192u
#define SKHI 16384u
#define SKLO 24576u
#define SVHI 32768u
#define SVLO 36864u
#define SM_BYTES 40960u

__global__ __launch_bounds__(128, 2)
void attn_kernel(const float* __restrict__ topo)
{
    __shared__ char sm[SM_BYTES];
    const uint32_t sb = smem_u32(sm);

    const int tid  = threadIdx.x;
    const int wid  = tid >> 5;
    const int lane = tid & 31;
    const int n0 = blockIdx.x * 64;      // q rows of this CTA
    const int h  = blockIdx.y, b = blockIdx.z;
    const int bh = b * Hx + h;
    const int qr0 = wid * 16;            // warp's q rows within tile

    const __nv_bfloat16* Qh = g_Qhi + ((size_t)bh * Nx + n0) * Fx;
    const __nv_bfloat16* Ql = g_Qlo + ((size_t)bh * Nx + n0) * Fx;
    const __nv_bfloat16* Kh = g_Khi + (size_t)bh * Nx * Fx;
    const __nv_bfloat16* Kl = g_Klo + (size_t)bh * Nx * Fx;
    const __nv_bfloat16* Vh = g_Vthi + (size_t)bh * HDx * Nx;
    const __nv_bfloat16* Vl = g_Vtlo + (size_t)bh * HDx * Nx;

    // ---- load Q tile (64x64 bf16 hi+lo) into swizzled smem ----
    #pragma unroll
    for (int i = 0; i < 4; i++) {
        int idx = tid + i * 128;          // 512 float4 per region
        int r = idx >> 3, seg = idx & 7;
        uint32_t so = sw128((uint32_t)(r * 128 + seg * 16));
        *(float4*)(sm + SQHI + so) = *(const float4*)(Qh + (size_t)r * Fx + seg * 8);
        *(float4*)(sm + SQLO + so) = *(const float4*)(Ql + (size_t)r * Fx + seg * 8);
    }
    __syncthreads();

    // ---- preload Q fragments (A operand), 4 ksteps x 4 regs, hi+lo ----
    uint32_t aQh[4][4], aQl[4][4];
    {
        int qrow = qr0 + (lane & 15);
        int colp = (lane >> 4) * 16;      // byte offset of 8-col block
        #pragma unroll
        for (int ks = 0; ks < 4; ks++) {
            uint32_t off = (uint32_t)(qrow * 128 + ks * 32 + colp);
            ldsm4(aQh[ks], sb + SQHI + sw128(off));
            ldsm4(aQl[ks], sb + SQLO + sw128(off));
        }
    }

    // B-fragment lane addressing (shared by K and V tiles)
    const int bnrow = (lane & 7) + ((lane >> 4) << 3);  // row within 16-row pair
    const int bkcol = ((lane >> 3) & 1) * 16;           // byte offset of k8 block

    float oc[4][4] = {};
    float lsum0 = 0.f, lsum1 = 0.f;

    const int trow = n0 + qr0 + (lane >> 2);
    const float* topoB = topo + ((size_t)b * Nx + trow) * Nx + (lane & 3) * 2;

    for (int t = 0; t < Nx / 64; t++) {
        const int m0 = t * 64;
        __syncthreads();   // previous tile's ldmatrix reads finished

        // ---- load K (hi+lo) and Vt (hi+lo) tiles into swizzled smem ----
        #pragma unroll
        for (int i = 0; i < 4; i++) {
            int idx = tid + i * 128;
            int r = idx >> 3, seg = idx & 7;
            uint32_t so = sw128((uint32_t)(r * 128 + seg * 16));
            *(float4*)(sm + SKHI + so) = *(const float4*)(Kh + (size_t)(m0 + r) * Fx + seg * 8);
            *(float4*)(sm + SKLO + so) = *(const float4*)(Kl + (size_t)(m0 + r) * Fx + seg * 8);
        }
        #pragma unroll
        for (int i = 0; i < 2; i++) {
            int idx = tid + i * 128;
            int d = idx >> 3, seg = idx & 7;
            uint32_t so = sw128((uint32_t)(d * 128 + seg * 16));
            *(float4*)(sm + SVHI + so) = *(const float4*)(Vh + (size_t)d * Nx + m0 + seg * 8);
            *(float4*)(sm + SVLO + so) = *(const float4*)(Vl + (size_t)d * Nx + m0 + seg * 8);
        }
        __syncthreads();

        // ---- topo loads straight into fragment lanes ----
        float2 tp0[8], tp1[8];
        {
            const float* p0 = topoB + m0;
            #pragma unroll
            for (int j = 0; j < 8; j++) {
                tp0[j] = *(const float2*)(p0 + j * 8);
                tp1[j] = *(const float2*)(p0 + 8 * Nx + j * 8);
            }
        }

        // ---- S = Qf . Kf^T (3-way split) ----
        float sc[8][4] = {};
        #pragma unroll
        for (int ks = 0; ks < 4; ks++) {
            uint32_t kb[16], kbl[16];
            #pragma unroll
            for (int p = 0; p < 4; p++) {
                uint32_t off = (uint32_t)((p * 16 + bnrow) * 128 + ks * 32 + bkcol);
                ldsm4(&kb[p * 4],  sb + SKHI + sw128(off));
                ldsm4(&kbl[p * 4], sb + SKLO + sw128(off));
            }
            #pragma unroll
            for (int j = 0; j < 8; j++) mma_bf16(sc[j], aQh[ks], &kb[j * 2]);
            #pragma unroll
            for (int j = 0; j < 8; j++) mma_bf16(sc[j], aQh[ks], &kbl[j * 2]);
            #pragma unroll
            for (int j = 0; j < 8; j++) mma_bf16(sc[j], aQl[ks], &kb[j * 2]);
        }

        // ---- epilogue: scale*topo, exp, pack to PV A-fragments ----
        uint32_t pAh[4][4], pAl[4][4];
        #pragma unroll
        for (int j = 0; j < 8; j++) {
            float p00 = __expf(fmaf(sc[j][0] * tp0[j].x, SCALEC, -SMAXC));
            float p01 = __expf(fmaf(sc[j][1] * tp0[j].y, SCALEC, -SMAXC));
            float p10 = __expf(fmaf(sc[j][2] * tp1[j].x, SCALEC, -SMAXC));
            float p11 = __expf(fmaf(sc[j][3] * tp1[j].y, SCALEC, -SMAXC));
            lsum0 += p00 + p01;
            lsum1 += p10 + p11;
            uint32_t h0 = packbf2(p00, p01);
            uint32_t h1 = packbf2(p10, p11);
            float e00 = p00 - __uint_as_float(h0 << 16);
            float e01 = p01 - __uint_as_float(h0 & 0xffff0000u);
            float e10 = p10 - __uint_as_float(h1 << 16);
            float e11 = p11 - __uint_as_float(h1 & 0xffff0000u);
            uint32_t l0 = packbf2(e00, e01);
            uint32_t l1 = packbf2(e10, e11);
            int ks = j >> 1, hf = (j & 1) * 2;
            pAh[ks][hf + 0] = h0;  pAh[ks][hf + 1] = h1;
            pAl[ks][hf + 0] = l0;  pAl[ks][hf + 1] = l1;
        }

        // ---- O += P @ V (3-way split) ----
        #pragma unroll
        for (int ks = 0; ks < 4; ks++) {
            uint32_t vb[8], vbl[8];
            #pragma unroll
            for (int p = 0; p < 2; p++) {
                uint32_t off = (uint32_t)((p * 16 + bnrow) * 128 + ks * 32 + bkcol);
                ldsm4(&vb[p * 4],  sb + SVHI + sw128(off));
                ldsm4(&vbl[p * 4], sb + SVLO + sw128(off));
            }
            #pragma unroll
            for (int jd = 0; jd < 4; jd++) mma_bf16(oc[jd], pAh[ks], &vb[jd * 2]);
            #pragma unroll
            for (int jd = 0; jd < 4; jd++) mma_bf16(oc[jd], pAl[ks], &vb[jd * 2]);
            #pragma unroll
            for (int jd = 0; jd < 4; jd++) mma_bf16(oc[jd], pAh[ks], &vbl[jd * 2]);
        }
    }

    // ---- finalize: reduce l over the quad, normalize, store ----
    lsum0 += __shfl_xor_sync(0xffffffffu, lsum0, 1);
    lsum0 += __shfl_xor_sync(0xffffffffu, lsum0, 2);
    lsum1 += __shfl_xor_sync(0xffffffffu, lsum1, 1);
    lsum1 += __shfl_xor_sync(0xffffffffu, lsum1, 2);
    const float inv0 = 1.0f / lsum0;
    const float inv1 = 1.0f / lsum1;

    const int r0 = n0 + qr0 + (lane >> 2);
    float* dst0 = g_AO + ((size_t)(b * Nx + r0)) * DIMx + h * HDx + (lane & 3) * 2;
    float* dst1 = dst0 + 8 * DIMx;
    #pragma unroll
    for (int jd = 0; jd < 4; jd++) {
        float2 v0 = make_float2(oc[jd][0] * inv0, oc[jd][1] * inv0);
        float2 v1 = make_float2(oc[jd][2] * inv1, oc[jd][3] * inv1);
        *(float2*)(dst0 + jd * 8) = v0;
        *(float2*)(dst1 + jd * 8) = v1;
    }
}

// ---------------------------------------------------------------------------
// Kernel 3: output projection out = AO @ Wo + bo
// ---------------------------------------------------------------------------
__global__ __launch_bounds__(256)
void proj_kernel(const float* __restrict__ Wo, const float* __restrict__ bo,
                 float* __restrict__ out)
{
    __shared__ float As[16][65];
    __shared__ float Bs[16][64];

    const int t  = threadIdx.x;
    const int ty = t >> 4, tx = t & 15;
    const int rowBase = blockIdx.y * 64;
    const int colBase = blockIdx.x * 64;

    float c[4][4] = {};

    for (int k0 = 0; k0 < DIMx; k0 += 16) {
        {
            int ar = t >> 2;
            int ak = (t & 3) * 4;
            float4 av = *(const float4*)&g_AO[(size_t)(rowBase + ar) * DIMx + k0 + ak];
            As[ak + 0][ar] = av.x; As[ak + 1][ar] = av.y;
            As[ak + 2][ar] = av.z; As[ak + 3][ar] = av.w;
            int bkk = t >> 4;
            int bn  = (t & 15) * 4;
            *(float4*)&Bs[bkk][bn] = *(const float4*)&Wo[(size_t)(k0 + bkk) * DIMx + colBase + bn];
        }
        __syncthreads();
        #pragma unroll
        for (int k = 0; k < 16; k++) {
            float a0 = As[k][ty*4+0], a1 = As[k][ty*4+1];
            float a2 = As[k][ty*4+2], a3 = As[k][ty*4+3];
            float4 b4 = *(const float4*)&Bs[k][tx*4];
            c[0][0] += a0*b4.x; c[0][1] += a0*b4.y; c[0][2] += a0*b4.z; c[0][3] += a0*b4.w;
            c[1][0] += a1*b4.x; c[1][1] += a1*b4.y; c[1][2] += a1*b4.z; c[1][3] += a1*b4.w;
            c[2][0] += a2*b4.x; c[2][1] += a2*b4.y; c[2][2] += a2*b4.z; c[2][3] += a2*b4.w;
            c[3][0] += a3*b4.x; c[3][1] += a3*b4.y; c[3][2] += a3*b4.z; c[3][3] += a3*b4.w;
        }
        __syncthreads();
    }

    #pragma unroll
    for (int i = 0; i < 4; i++) {
        int row = rowBase + ty*4 + i;
        #pragma unroll
        for (int j = 0; j < 4; j++) {
            int col = colBase + tx*4 + j;
            out[(size_t)row * DIMx + col] = c[i][j] + bo[col];
        }
    }
}

// ---------------------------------------------------------------------------
extern "C" void kernel_launch(void* const* d_in, const int* in_sizes, int n_in,
                              void* d_out, int out_size)
{
    const float* x    = (const float*)d_in[0];
    const float* topo = (const float*)d_in[1];
    const float* Wq   = (const float*)d_in[2];
    const float* bq   = (const float*)d_in[3];
    const float* Wk   = (const float*)d_in[4];
    const float* bk   = (const float*)d_in[5];
    const float* Wv   = (const float*)d_in[6];
    const float* bv   = (const float*)d_in[7];
    const float* Wo   = (const float*)d_in[8];
    const float* bo   = (const float*)d_in[9];
    float* out = (float*)d_out;
    (void)in_sizes; (void)n_in; (void)out_size;

    dim3 gq(DIMx / 64, MTOT / 64, 3);
    qkv_kernel<<<gq, 256>>>(x, Wq, bq, Wk, bk, Wv, bv);

    dim3 ga(Nx / 64, Hx, Bx);
    attn_kernel<<<ga, 128>>>(topo);

    dim3 go(DIMx / 64, MTOT / 64);
    proj_kernel<<<go, 256>>>(Wo, bo, out);
}

// round 5
// speedup vs baseline: 3.3359x; 1.5369x over previous
#include <cuda_runtime.h>
#include <cuda_bf16.h>
#include <math.h>
#include <stdint.h>

#define Bx 4
#define Nx 2048
#define DIMx 256
#define Hx 8
#define HDx 32
#define Fx 64
#define MTOT (Bx*Nx)

// ------------------------- device scratch (no allocs) -----------------------
__device__ __nv_bfloat16 g_Xh[MTOT*DIMx];
__device__ __nv_bfloat16 g_Xl[MTOT*DIMx];
__device__ __nv_bfloat16 g_Wth[4*DIMx*DIMx];   // transposed weights [mode][n][k]
__device__ __nv_bfloat16 g_Wtl[4*DIMx*DIMx];
__device__ __nv_bfloat16 g_Qhi[Bx*Hx*Nx*Fx];
__device__ __nv_bfloat16 g_Qlo[Bx*Hx*Nx*Fx];
__device__ __nv_bfloat16 g_Khi[Bx*Hx*Nx*Fx];
__device__ __nv_bfloat16 g_Klo[Bx*Hx*Nx*Fx];
__device__ __nv_bfloat16 g_Vthi[Bx*Hx*HDx*Nx];   // [bh][d][n]
__device__ __nv_bfloat16 g_Vtlo[Bx*Hx*HDx*Nx];
__device__ __nv_bfloat16 g_AOh[MTOT*DIMx];
__device__ __nv_bfloat16 g_AOl[MTOT*DIMx];

// ------------------------- helpers ------------------------------------------
__device__ __forceinline__ uint32_t smem_u32(const void* p) {
    uint32_t a;
    asm("{ .reg .u64 t; cvta.to.shared.u64 t, %1; cvt.u32.u64 %0, t; }" : "=r"(a) : "l"(p));
    return a;
}
__device__ __forceinline__ uint32_t packbf2(float lo, float hi) {
    uint32_t r;
    asm("cvt.rn.bf16x2.f32 %0, %1, %2;" : "=r"(r) : "f"(hi), "f"(lo));
    return r;   // lo -> bits[15:0], hi -> bits[31:16]
}
__device__ __forceinline__ void split2(float v0, float v1, uint32_t& hp, uint32_t& lp) {
    hp = packbf2(v0, v1);
    float h0 = __uint_as_float(hp << 16), h1 = __uint_as_float(hp & 0xffff0000u);
    lp = packbf2(v0 - h0, v1 - h1);
}
__device__ __forceinline__ void ldsm4(uint32_t* r, uint32_t addr) {
    asm volatile("ldmatrix.sync.aligned.m8n8.x4.shared.b16 {%0,%1,%2,%3}, [%4];"
        : "=r"(r[0]), "=r"(r[1]), "=r"(r[2]), "=r"(r[3]) : "r"(addr));
}
__device__ __forceinline__ void mma_bf16(float* c, const uint32_t* a, const uint32_t* b) {
    asm volatile("mma.sync.aligned.m16n8k16.row.col.f32.bf16.bf16.f32 "
        "{%0,%1,%2,%3}, {%4,%5,%6,%7}, {%8,%9}, {%0,%1,%2,%3};"
        : "+f"(c[0]), "+f"(c[1]), "+f"(c[2]), "+f"(c[3])
        : "r"(a[0]), "r"(a[1]), "r"(a[2]), "r"(a[3]), "r"(b[0]), "r"(b[1]));
}
__device__ __forceinline__ uint32_t sw128(uint32_t off) {
    return off ^ ((off >> 3) & 0x70);
}
__device__ __forceinline__ void cp16(uint32_t dst, const void* src) {
    asm volatile("cp.async.cg.shared.global [%0], [%1], 16;" :: "r"(dst), "l"(src) : "memory");
}
#define CP_COMMIT() asm volatile("cp.async.commit_group;" ::: "memory")

// ---------------------------------------------------------------------------
// Prep: split X to bf16 hi/lo; transpose+split the 4 weight matrices
// ---------------------------------------------------------------------------
__global__ __launch_bounds__(256)
void split_x_kernel(const float* __restrict__ x)
{
    int idx4 = blockIdx.x * 256 + threadIdx.x;   // 524288 float4s
    float4 v = ((const float4*)x)[idx4];
    uint32_t h0, l0, h1, l1;
    split2(v.x, v.y, h0, l0);
    split2(v.z, v.w, h1, l1);
    ((uint2*)g_Xh)[idx4] = make_uint2(h0, h1);
    ((uint2*)g_Xl)[idx4] = make_uint2(l0, l1);
}

__global__ __launch_bounds__(256)
void split_w_kernel(const float* __restrict__ Wq, const float* __restrict__ Wk,
                    const float* __restrict__ Wv, const float* __restrict__ Wo)
{
    int mode = blockIdx.x >> 8;
    const float* W = (mode == 0) ? Wq : (mode == 1) ? Wk : (mode == 2) ? Wv : Wo;
    int e = (blockIdx.x & 255) * 256 + threadIdx.x;  // 65536 per mode
    int n = e >> 8, k = e & 255;
    float w = W[k * 256 + n];
    __nv_bfloat16 h = __float2bfloat16(w);
    float lo = w - __bfloat162float(h);
    g_Wth[mode * 65536 + e] = h;
    g_Wtl[mode * 65536 + e] = __float2bfloat16(lo);
}

// ---------------------------------------------------------------------------
// GEMM kernel (HMMA split-bf16 3-term): C[64x64] = A[64x256] @ Wt[64x256]^T
// mode 0=Q, 1=K (sincos feature epilogue), 2=V (transpose epilogue),
// 3=out-projection (bias + fp32 store)
// ---------------------------------------------------------------------------
#define GAH 0u
#define GAL 8192u
#define GBH 16384u
#define GBL 24576u

__global__ __launch_bounds__(128)
void gemm_kernel(int mode_base,
                 const float* __restrict__ bq, const float* __restrict__ bk,
                 const float* __restrict__ bv, const float* __restrict__ bo,
                 float* __restrict__ out)
{
    __shared__ char sm[32768];
    const uint32_t sb = smem_u32(sm);
    const int tid = threadIdx.x;
    const int wid = tid >> 5, lane = tid & 31;
    const int mode = mode_base + blockIdx.z;
    const int rowBase = blockIdx.y * 64;
    const int colBase = blockIdx.x * 64;

    const __nv_bfloat16* Ah = (mode < 3) ? g_Xh : g_AOh;
    const __nv_bfloat16* Al = (mode < 3) ? g_Xl : g_AOl;
    const __nv_bfloat16* Bth = g_Wth + mode * 65536;
    const __nv_bfloat16* Btl = g_Wtl + mode * 65536;
    const float* bias = (mode == 0) ? bq : (mode == 1) ? bk : (mode == 2) ? bv : bo;

    const int bnrow = (lane & 7) + ((lane >> 4) << 3);
    const int bkcol = ((lane >> 3) & 1) * 16;
    const uint32_t aoff_base = (uint32_t)((wid * 16 + (lane & 15)) * 128 + (lane >> 4) * 16);

    float sc[8][4] = {};

    for (int kc = 0; kc < 4; kc++) {
        __syncthreads();
        #pragma unroll
        for (int i = 0; i < 4; i++) {
            int idx = tid + i * 128;
            int r = idx >> 3, seg = idx & 7;
            uint32_t so = sw128((uint32_t)(r * 128 + seg * 16));
            *(float4*)(sm + GAH + so) = *(const float4*)(Ah + (size_t)(rowBase + r) * 256 + kc * 64 + seg * 8);
            *(float4*)(sm + GAL + so) = *(const float4*)(Al + (size_t)(rowBase + r) * 256 + kc * 64 + seg * 8);
            *(float4*)(sm + GBH + so) = *(const float4*)(Bth + (size_t)(colBase + r) * 256 + kc * 64 + seg * 8);
            *(float4*)(sm + GBL + so) = *(const float4*)(Btl + (size_t)(colBase + r) * 256 + kc * 64 + seg * 8);
        }
        __syncthreads();

        #pragma unroll
        for (int ks = 0; ks < 4; ks++) {
            uint32_t ah[4], al[4], kb[16], kbl[16];
            uint32_t aoff = sw128(aoff_base + ks * 32);
            ldsm4(ah, sb + GAH + aoff);
            ldsm4(al, sb + GAL + aoff);
            #pragma unroll
            for (int p = 0; p < 4; p++) {
                uint32_t off = sw128((uint32_t)((p * 16 + bnrow) * 128 + ks * 32 + bkcol));
                ldsm4(&kb[p * 4],  sb + GBH + off);
                ldsm4(&kbl[p * 4], sb + GBL + off);
            }
            #pragma unroll
            for (int j = 0; j < 8; j++) mma_bf16(sc[j], ah, &kb[j * 2]);
            #pragma unroll
            for (int j = 0; j < 8; j++) mma_bf16(sc[j], ah, &kbl[j * 2]);
            #pragma unroll
            for (int j = 0; j < 8; j++) mma_bf16(sc[j], al, &kb[j * 2]);
        }
    }

    // ------------------ epilogues ------------------
    const int row0 = rowBase + wid * 16 + (lane >> 2);

    if (mode <= 1) {
        __nv_bfloat16* dhi = (mode == 0) ? g_Qhi : g_Khi;
        __nv_bfloat16* dlo = (mode == 0) ? g_Qlo : g_Klo;
        #pragma unroll
        for (int j = 0; j < 8; j++) {
            int col0 = colBase + j * 8 + (lane & 3) * 2;
            int h = col0 >> 5, d0 = col0 & 31;
            float b0 = __ldg(&bias[col0]), b1 = __ldg(&bias[col0 + 1]);
            #pragma unroll
            for (int half = 0; half < 2; half++) {
                int row = row0 + half * 8;
                int bb = row >> 11, n = row & (Nx - 1);
                float v0 = sc[j][half * 2 + 0] + b0;
                float v1 = sc[j][half * 2 + 1] + b1;
                float sn0, cn0, sn1, cn1;
                sincosf(v0, &sn0, &cn0);
                sincosf(v1, &sn1, &cn1);
                size_t fb = ((size_t)(bb * Hx + h) * Nx + n) * Fx;
                uint32_t hp, lp;
                split2(cn0, cn1, hp, lp);
                *(uint32_t*)&dhi[fb + d0] = hp;
                *(uint32_t*)&dlo[fb + d0] = lp;
                split2(sn0, sn1, hp, lp);
                *(uint32_t*)&dhi[fb + 32 + d0] = hp;
                *(uint32_t*)&dlo[fb + 32 + d0] = lp;
            }
        }
    } else if (mode == 3) {
        #pragma unroll
        for (int j = 0; j < 8; j++) {
            int col0 = colBase + j * 8 + (lane & 3) * 2;
            float b0 = __ldg(&bias[col0]), b1 = __ldg(&bias[col0 + 1]);
            #pragma unroll
            for (int half = 0; half < 2; half++) {
                int row = row0 + half * 8;
                float2 v = make_float2(sc[j][half * 2 + 0] + b0, sc[j][half * 2 + 1] + b1);
                *(float2*)&out[(size_t)row * 256 + col0] = v;
            }
        }
    } else {
        // mode 2: V — split + smem transpose + store [bh][d][n]
        __syncthreads();
        __nv_bfloat16* svh = (__nv_bfloat16*)sm;           // [64][66]
        __nv_bfloat16* svl = svh + 64 * 66;
        #pragma unroll
        for (int j = 0; j < 8; j++) {
            int c0 = j * 8 + (lane & 3) * 2;
            float b0 = __ldg(&bias[colBase + c0]), b1 = __ldg(&bias[colBase + c0 + 1]);
            #pragma unroll
            for (int half = 0; half < 2; half++) {
                int mrow = wid * 16 + (lane >> 2) + half * 8;
                float v0 = sc[j][half * 2 + 0] + b0;
                float v1 = sc[j][half * 2 + 1] + b1;
                __nv_bfloat16 h0 = __float2bfloat16(v0);
                __nv_bfloat16 h1 = __float2bfloat16(v1);
                svh[mrow * 66 + c0]     = h0;
                svh[mrow * 66 + c0 + 1] = h1;
                svl[mrow * 66 + c0]     = __float2bfloat16(v0 - __bfloat162float(h0));
                svl[mrow * 66 + c0 + 1] = __float2bfloat16(v1 - __bfloat162float(h1));
            }
        }
        __syncthreads();
        // read phase: each thread handles one column d (0..63) and 32 tokens
        int d   = tid >> 1;               // 0..63  (FIX: full 64 columns)
        int nch = (tid & 1) * 32;         // 0 or 32
        int colg = colBase + d;
        int h = colg >> 5, dd = colg & 31;
        int bb = rowBase >> 11;
        int nt = (rowBase & (Nx - 1)) + nch;
        uint32_t ph[16], pl[16];
        #pragma unroll
        for (int m = 0; m < 16; m++) {
            uint32_t a0 = *(const unsigned short*)&svh[(nch + 2 * m) * 66 + d];
            uint32_t a1 = *(const unsigned short*)&svh[(nch + 2 * m + 1) * 66 + d];
            ph[m] = a0 | (a1 << 16);
            uint32_t b0 = *(const unsigned short*)&svl[(nch + 2 * m) * 66 + d];
            uint32_t b1 = *(const unsigned short*)&svl[(nch + 2 * m + 1) * 66 + d];
            pl[m] = b0 | (b1 << 16);
        }
        size_t base = ((size_t)((bb * Hx + h) * HDx + dd)) * Nx + nt;
        #pragma unroll
        for (int q = 0; q < 4; q++) {
            *(uint4*)&g_Vthi[base + q * 8] = make_uint4(ph[q*4+0], ph[q*4+1], ph[q*4+2], ph[q*4+3]);
            *(uint4*)&g_Vtlo[base + q * 8] = make_uint4(pl[q*4+0], pl[q*4+1], pl[q*4+2], pl[q*4+3]);
        }
    }
}

// ---------------------------------------------------------------------------
// Attention kernel: mma.sync flash attention, cp.async double-buffered KV
// ---------------------------------------------------------------------------
#define SCALEC 0.35355339059327373f
#define SMAXC  11.4f

#define SQHI 0u
#define SQLO 8192u
#define BUF0 16384u
#define BUFSTRIDE 24576u
#define KHO 0u
#define KLO_ 8192u
#define VHO 16384u
#define VLO_ 20480u
#define ATTN_SMEM 65536u

__device__ __forceinline__ void issue_kv(uint32_t sb, uint32_t buf, int m0,
                                         const __nv_bfloat16* Kh, const __nv_bfloat16* Kl,
                                         const __nv_bfloat16* Vh, const __nv_bfloat16* Vl,
                                         int tid)
{
    #pragma unroll
    for (int i = 0; i < 4; i++) {
        int idx = tid + i * 128;
        int r = idx >> 3, seg = idx & 7;
        uint32_t so = sw128((uint32_t)(r * 128 + seg * 16));
        cp16(sb + buf + KHO  + so, Kh + (size_t)(m0 + r) * Fx + seg * 8);
        cp16(sb + buf + KLO_ + so, Kl + (size_t)(m0 + r) * Fx + seg * 8);
    }
    #pragma unroll
    for (int i = 0; i < 2; i++) {
        int idx = tid + i * 128;
        int d = idx >> 3, seg = idx & 7;
        uint32_t so = sw128((uint32_t)(d * 128 + seg * 16));
        cp16(sb + buf + VHO  + so, Vh + (size_t)d * Nx + m0 + seg * 8);
        cp16(sb + buf + VLO_ + so, Vl + (size_t)d * Nx + m0 + seg * 8);
    }
}

__global__ __launch_bounds__(128, 2)
void attn_kernel(const float* __restrict__ topo)
{
    extern __shared__ char sm[];
    const uint32_t sb = smem_u32(sm);

    const int tid  = threadIdx.x;
    const int wid  = tid >> 5;
    const int lane = tid & 31;
    const int n0 = blockIdx.x * 64;
    const int h  = blockIdx.y, b = blockIdx.z;
    const int bh = b * Hx + h;
    const int qr0 = wid * 16;

    const __nv_bfloat16* Qh = g_Qhi + ((size_t)bh * Nx + n0) * Fx;
    const __nv_bfloat16* Ql = g_Qlo + ((size_t)bh * Nx + n0) * Fx;
    const __nv_bfloat16* Kh = g_Khi + (size_t)bh * Nx * Fx;
    const __nv_bfloat16* Kl = g_Klo + (size_t)bh * Nx * Fx;
    const __nv_bfloat16* Vh = g_Vthi + (size_t)bh * HDx * Nx;
    const __nv_bfloat16* Vl = g_Vtlo + (size_t)bh * HDx * Nx;

    // Q tile -> smem
    #pragma unroll
    for (int i = 0; i < 4; i++) {
        int idx = tid + i * 128;
        int r = idx >> 3, seg = idx & 7;
        uint32_t so = sw128((uint32_t)(r * 128 + seg * 16));
        *(float4*)(sm + SQHI + so) = *(const float4*)(Qh + (size_t)r * Fx + seg * 8);
        *(float4*)(sm + SQLO + so) = *(const float4*)(Ql + (size_t)r * Fx + seg * 8);
    }
    // prologue: prefetch KV tile 0
    issue_kv(sb, BUF0, 0, Kh, Kl, Vh, Vl, tid);
    CP_COMMIT();
    __syncthreads();

    // Q fragments
    uint32_t aQh[4][4], aQl[4][4];
    {
        int qrow = qr0 + (lane & 15);
        int colp = (lane >> 4) * 16;
        #pragma unroll
        for (int ks = 0; ks < 4; ks++) {
            uint32_t off = sw128((uint32_t)(qrow * 128 + ks * 32 + colp));
            ldsm4(aQh[ks], sb + SQHI + off);
            ldsm4(aQl[ks], sb + SQLO + off);
        }
    }

    const int bnrow = (lane & 7) + ((lane >> 4) << 3);
    const int bkcol = ((lane >> 3) & 1) * 16;

    float oc[4][4] = {};
    float lsum0 = 0.f, lsum1 = 0.f;

    const int trow = n0 + qr0 + (lane >> 2);
    const float* topoB = topo + ((size_t)b * Nx + trow) * Nx + (lane & 3) * 2;

    for (int t = 0; t < Nx / 64; t++) {
        const int m0 = t * 64;
        const uint32_t buf = BUF0 + (uint32_t)(t & 1) * BUFSTRIDE;

        if (t + 1 < Nx / 64) {
            issue_kv(sb, BUF0 + (uint32_t)((t + 1) & 1) * BUFSTRIDE, m0 + 64,
                     Kh, Kl, Vh, Vl, tid);
            CP_COMMIT();
            asm volatile("cp.async.wait_group 1;" ::: "memory");
        } else {
            asm volatile("cp.async.wait_group 0;" ::: "memory");
        }
        __syncthreads();

        // topo loads straight into fragment lanes (hidden behind S-MMA)
        float2 tp0[8], tp1[8];
        {
            const float* p0 = topoB + m0;
            #pragma unroll
            for (int j = 0; j < 8; j++) {
                tp0[j] = *(const float2*)(p0 + j * 8);
                tp1[j] = *(const float2*)(p0 + 8 * Nx + j * 8);
            }
        }

        // S = Qf . Kf^T (3-way split)
        float scr[8][4] = {};
        #pragma unroll
        for (int ks = 0; ks < 4; ks++) {
            uint32_t kb[16], kbl[16];
            #pragma unroll
            for (int p = 0; p < 4; p++) {
                uint32_t off = sw128((uint32_t)((p * 16 + bnrow) * 128 + ks * 32 + bkcol));
                ldsm4(&kb[p * 4],  sb + buf + KHO  + off);
                ldsm4(&kbl[p * 4], sb + buf + KLO_ + off);
            }
            #pragma unroll
            for (int j = 0; j < 8; j++) mma_bf16(scr[j], aQh[ks], &kb[j * 2]);
            #pragma unroll
            for (int j = 0; j < 8; j++) mma_bf16(scr[j], aQh[ks], &kbl[j * 2]);
            #pragma unroll
            for (int j = 0; j < 8; j++) mma_bf16(scr[j], aQl[ks], &kb[j * 2]);
        }

        // epilogue: scale*topo, exp, pack to PV A-fragments
        uint32_t pAh[4][4], pAl[4][4];
        #pragma unroll
        for (int j = 0; j < 8; j++) {
            float p00 = __expf(fmaf(scr[j][0] * tp0[j].x, SCALEC, -SMAXC));
            float p01 = __expf(fmaf(scr[j][1] * tp0[j].y, SCALEC, -SMAXC));
            float p10 = __expf(fmaf(scr[j][2] * tp1[j].x, SCALEC, -SMAXC));
            float p11 = __expf(fmaf(scr[j][3] * tp1[j].y, SCALEC, -SMAXC));
            lsum0 += p00 + p01;
            lsum1 += p10 + p11;
            uint32_t h0, l0, h1, l1;
            split2(p00, p01, h0, l0);
            split2(p10, p11, h1, l1);
            int ks = j >> 1, hf = (j & 1) * 2;
            pAh[ks][hf + 0] = h0;  pAh[ks][hf + 1] = h1;
            pAl[ks][hf + 0] = l0;  pAl[ks][hf + 1] = l1;
        }

        // O += P @ V (3-way split)
        #pragma unroll
        for (int ks = 0; ks < 4; ks++) {
            uint32_t vb[8], vbl[8];
            #pragma unroll
            for (int p = 0; p < 2; p++) {
                uint32_t off = sw128((uint32_t)((p * 16 + bnrow) * 128 + ks * 32 + bkcol));
                ldsm4(&vb[p * 4],  sb + buf + VHO  + off);
                ldsm4(&vbl[p * 4], sb + buf + VLO_ + off);
            }
            #pragma unroll
            for (int jd = 0; jd < 4; jd++) mma_bf16(oc[jd], pAh[ks], &vb[jd * 2]);
            #pragma unroll
            for (int jd = 0; jd < 4; jd++) mma_bf16(oc[jd], pAl[ks], &vb[jd * 2]);
            #pragma unroll
            for (int jd = 0; jd < 4; jd++) mma_bf16(oc[jd], pAh[ks], &vbl[jd * 2]);
        }
        __syncthreads();
    }

    // finalize: reduce l over the quad, normalize, split-store O
    lsum0 += __shfl_xor_sync(0xffffffffu, lsum0, 1);
    lsum0 += __shfl_xor_sync(0xffffffffu, lsum0, 2);
    lsum1 += __shfl_xor_sync(0xffffffffu, lsum1, 1);
    lsum1 += __shfl_xor_sync(0xffffffffu, lsum1, 2);
    const float inv0 = 1.0f / lsum0;
    const float inv1 = 1.0f / lsum1;

    const int r0 = n0 + qr0 + (lane >> 2);
    size_t base0 = ((size_t)(b * Nx + r0)) * DIMx + h * HDx + (lane & 3) * 2;
    size_t base1 = base0 + 8 * DIMx;
    #pragma unroll
    for (int jd = 0; jd < 4; jd++) {
        uint32_t hp, lp;
        split2(oc[jd][0] * inv0, oc[jd][1] * inv0, hp, lp);
        *(uint32_t*)&g_AOh[base0 + jd * 8] = hp;
        *(uint32_t*)&g_AOl[base0 + jd * 8] = lp;
        split2(oc[jd][2] * inv1, oc[jd][3] * inv1, hp, lp);
        *(uint32_t*)&g_AOh[base1 + jd * 8] = hp;
        *(uint32_t*)&g_AOl[base1 + jd * 8] = lp;
    }
}

// ---------------------------------------------------------------------------
extern "C" void kernel_launch(void* const* d_in, const int* in_sizes, int n_in,
                              void* d_out, int out_size)
{
    const float* x    = (const float*)d_in[0];
    const float* topo = (const float*)d_in[1];
    const float* Wq   = (const float*)d_in[2];
    const float* bq   = (const float*)d_in[3];
    const float* Wk   = (const float*)d_in[4];
    const float* bk   = (const float*)d_in[5];
    const float* Wv   = (const float*)d_in[6];
    const float* bv   = (const float*)d_in[7];
    const float* Wo   = (const float*)d_in[8];
    const float* bo   = (const float*)d_in[9];
    float* out = (float*)d_out;
    (void)in_sizes; (void)n_in; (void)out_size;

    cudaFuncSetAttribute(attn_kernel,
                         cudaFuncAttributeMaxDynamicSharedMemorySize, ATTN_SMEM);

    split_x_kernel<<<2048, 256>>>(x);
    split_w_kernel<<<1024, 256>>>(Wq, Wk, Wv, Wo);

    dim3 gq(4, 128, 3);
    gemm_kernel<<<gq, 128>>>(0, bq, bk, bv, bo, out);

    dim3 ga(Nx / 64, Hx, Bx);
    attn_kernel<<<ga, 128, ATTN_SMEM>>>(topo);

    dim3 go(4, 128, 1);
    gemm_kernel<<<go, 128>>>(3, bq, bk, bv, bo, out);
}

// round 6
// speedup vs baseline: 3.3571x; 1.0064x over previous
#include <cuda_runtime.h>
#include <cuda_bf16.h>
#include <math.h>
#include <stdint.h>

#define Bx 4
#define Nx 2048
#define DIMx 256
#define Hx 8
#define HDx 32
#define Fx 64
#define MTOT (Bx*Nx)

// ------------------------- device scratch (no allocs) -----------------------
__device__ __nv_bfloat16 g_Xh[MTOT*DIMx];
__device__ __nv_bfloat16 g_Xl[MTOT*DIMx];
__device__ __nv_bfloat16 g_Wth[4*DIMx*DIMx];   // transposed weights [mode][n][k]
__device__ __nv_bfloat16 g_Wtl[4*DIMx*DIMx];
__device__ __nv_bfloat16 g_Qhi[Bx*Hx*Nx*Fx];
__device__ __nv_bfloat16 g_Qlo[Bx*Hx*Nx*Fx];
__device__ __nv_bfloat16 g_Khi[Bx*Hx*Nx*Fx];
__device__ __nv_bfloat16 g_Klo[Bx*Hx*Nx*Fx];
__device__ __nv_bfloat16 g_Vthi[Bx*Hx*HDx*Nx];   // [bh][d][n]
__device__ __nv_bfloat16 g_Vtlo[Bx*Hx*HDx*Nx];
__device__ __nv_bfloat16 g_AOh[MTOT*DIMx];
__device__ __nv_bfloat16 g_AOl[MTOT*DIMx];

// ------------------------- helpers ------------------------------------------
__device__ __forceinline__ uint32_t smem_u32(const void* p) {
    uint32_t a;
    asm("{ .reg .u64 t; cvta.to.shared.u64 t, %1; cvt.u32.u64 %0, t; }" : "=r"(a) : "l"(p));
    return a;
}
__device__ __forceinline__ uint32_t packbf2(float lo, float hi) {
    uint32_t r;
    asm("cvt.rn.bf16x2.f32 %0, %1, %2;" : "=r"(r) : "f"(hi), "f"(lo));
    return r;   // lo -> bits[15:0], hi -> bits[31:16]
}
__device__ __forceinline__ void split2(float v0, float v1, uint32_t& hp, uint32_t& lp) {
    hp = packbf2(v0, v1);
    float h0 = __uint_as_float(hp << 16), h1 = __uint_as_float(hp & 0xffff0000u);
    lp = packbf2(v0 - h0, v1 - h1);
}
__device__ __forceinline__ void ldsm4(uint32_t* r, uint32_t addr) {
    asm volatile("ldmatrix.sync.aligned.m8n8.x4.shared.b16 {%0,%1,%2,%3}, [%4];"
        : "=r"(r[0]), "=r"(r[1]), "=r"(r[2]), "=r"(r[3]) : "r"(addr));
}
__device__ __forceinline__ void mma_bf16(float* c, const uint32_t* a, const uint32_t* b) {
    asm volatile("mma.sync.aligned.m16n8k16.row.col.f32.bf16.bf16.f32 "
        "{%0,%1,%2,%3}, {%4,%5,%6,%7}, {%8,%9}, {%0,%1,%2,%3};"
        : "+f"(c[0]), "+f"(c[1]), "+f"(c[2]), "+f"(c[3])
        : "r"(a[0]), "r"(a[1]), "r"(a[2]), "r"(a[3]), "r"(b[0]), "r"(b[1]));
}
__device__ __forceinline__ uint32_t sw128(uint32_t off) {
    return off ^ ((off >> 3) & 0x70);
}
__device__ __forceinline__ void cp16(uint32_t dst, const void* src) {
    asm volatile("cp.async.cg.shared.global [%0], [%1], 16;" :: "r"(dst), "l"(src) : "memory");
}
#define CP_COMMIT() asm volatile("cp.async.commit_group;" ::: "memory")

// ---------------------------------------------------------------------------
// Prep: split X to bf16 hi/lo; transpose+split the 4 weight matrices
// ---------------------------------------------------------------------------
__global__ __launch_bounds__(256)
void split_x_kernel(const float* __restrict__ x)
{
    int idx4 = blockIdx.x * 256 + threadIdx.x;   // 524288 float4s
    float4 v = ((const float4*)x)[idx4];
    uint32_t h0, l0, h1, l1;
    split2(v.x, v.y, h0, l0);
    split2(v.z, v.w, h1, l1);
    ((uint2*)g_Xh)[idx4] = make_uint2(h0, h1);
    ((uint2*)g_Xl)[idx4] = make_uint2(l0, l1);
}

__global__ __launch_bounds__(256)
void split_w_kernel(const float* __restrict__ Wq, const float* __restrict__ Wk,
                    const float* __restrict__ Wv, const float* __restrict__ Wo)
{
    int mode = blockIdx.x >> 8;
    const float* W = (mode == 0) ? Wq : (mode == 1) ? Wk : (mode == 2) ? Wv : Wo;
    int e = (blockIdx.x & 255) * 256 + threadIdx.x;  // 65536 per mode
    int n = e >> 8, k = e & 255;
    float w = W[k * 256 + n];
    __nv_bfloat16 h = __float2bfloat16(w);
    float lo = w - __bfloat162float(h);
    g_Wth[mode * 65536 + e] = h;
    g_Wtl[mode * 65536 + e] = __float2bfloat16(lo);
}

// ---------------------------------------------------------------------------
// GEMM kernel (HMMA split-bf16 3-term): C[64x64] = A[64x256] @ Wt[64x256]^T
// mode 0=Q, 1=K (sincos feature epilogue), 2=V (transpose epilogue),
// 3=out-projection (bias + fp32 store)
// ---------------------------------------------------------------------------
#define GAH 0u
#define GAL 8192u
#define GBH 16384u
#define GBL 24576u

__global__ __launch_bounds__(128)
void gemm_kernel(int mode_base,
                 const float* __restrict__ bq, const float* __restrict__ bk,
                 const float* __restrict__ bv, const float* __restrict__ bo,
                 float* __restrict__ out)
{
    __shared__ char sm[32768];
    const uint32_t sb = smem_u32(sm);
    const int tid = threadIdx.x;
    const int wid = tid >> 5, lane = tid & 31;
    const int mode = mode_base + blockIdx.z;
    const int rowBase = blockIdx.y * 64;
    const int colBase = blockIdx.x * 64;

    const __nv_bfloat16* Ah = (mode < 3) ? g_Xh : g_AOh;
    const __nv_bfloat16* Al = (mode < 3) ? g_Xl : g_AOl;
    const __nv_bfloat16* Bth = g_Wth + mode * 65536;
    const __nv_bfloat16* Btl = g_Wtl + mode * 65536;
    const float* bias = (mode == 0) ? bq : (mode == 1) ? bk : (mode == 2) ? bv : bo;

    const int bnrow = (lane & 7) + ((lane >> 4) << 3);
    const int bkcol = ((lane >> 3) & 1) * 16;
    const uint32_t aoff_base = (uint32_t)((wid * 16 + (lane & 15)) * 128 + (lane >> 4) * 16);

    float sc[8][4] = {};

    for (int kc = 0; kc < 4; kc++) {
        __syncthreads();
        #pragma unroll
        for (int i = 0; i < 4; i++) {
            int idx = tid + i * 128;
            int r = idx >> 3, seg = idx & 7;
            uint32_t so = sw128((uint32_t)(r * 128 + seg * 16));
            *(float4*)(sm + GAH + so) = *(const float4*)(Ah + (size_t)(rowBase + r) * 256 + kc * 64 + seg * 8);
            *(float4*)(sm + GAL + so) = *(const float4*)(Al + (size_t)(rowBase + r) * 256 + kc * 64 + seg * 8);
            *(float4*)(sm + GBH + so) = *(const float4*)(Bth + (size_t)(colBase + r) * 256 + kc * 64 + seg * 8);
            *(float4*)(sm + GBL + so) = *(const float4*)(Btl + (size_t)(colBase + r) * 256 + kc * 64 + seg * 8);
        }
        __syncthreads();

        #pragma unroll
        for (int ks = 0; ks < 4; ks++) {
            uint32_t ah[4], al[4], kb[16], kbl[16];
            uint32_t aoff = sw128(aoff_base + ks * 32);
            ldsm4(ah, sb + GAH + aoff);
            ldsm4(al, sb + GAL + aoff);
            #pragma unroll
            for (int p = 0; p < 4; p++) {
                uint32_t off = sw128((uint32_t)((p * 16 + bnrow) * 128 + ks * 32 + bkcol));
                ldsm4(&kb[p * 4],  sb + GBH + off);
                ldsm4(&kbl[p * 4], sb + GBL + off);
            }
            #pragma unroll
            for (int j = 0; j < 8; j++) mma_bf16(sc[j], ah, &kb[j * 2]);
            #pragma unroll
            for (int j = 0; j < 8; j++) mma_bf16(sc[j], ah, &kbl[j * 2]);
            #pragma unroll
            for (int j = 0; j < 8; j++) mma_bf16(sc[j], al, &kb[j * 2]);
        }
    }

    // ------------------ epilogues ------------------
    const int row0 = rowBase + wid * 16 + (lane >> 2);

    if (mode <= 1) {
        __nv_bfloat16* dhi = (mode == 0) ? g_Qhi : g_Khi;
        __nv_bfloat16* dlo = (mode == 0) ? g_Qlo : g_Klo;
        #pragma unroll
        for (int j = 0; j < 8; j++) {
            int col0 = colBase + j * 8 + (lane & 3) * 2;
            int h = col0 >> 5, d0 = col0 & 31;
            float b0 = __ldg(&bias[col0]), b1 = __ldg(&bias[col0 + 1]);
            #pragma unroll
            for (int half = 0; half < 2; half++) {
                int row = row0 + half * 8;
                int bb = row >> 11, n = row & (Nx - 1);
                float v0 = sc[j][half * 2 + 0] + b0;
                float v1 = sc[j][half * 2 + 1] + b1;
                float sn0, cn0, sn1, cn1;
                sincosf(v0, &sn0, &cn0);
                sincosf(v1, &sn1, &cn1);
                size_t fb = ((size_t)(bb * Hx + h) * Nx + n) * Fx;
                uint32_t hp, lp;
                split2(cn0, cn1, hp, lp);
                *(uint32_t*)&dhi[fb + d0] = hp;
                *(uint32_t*)&dlo[fb + d0] = lp;
                split2(sn0, sn1, hp, lp);
                *(uint32_t*)&dhi[fb + 32 + d0] = hp;
                *(uint32_t*)&dlo[fb + 32 + d0] = lp;
            }
        }
    } else if (mode == 3) {
        #pragma unroll
        for (int j = 0; j < 8; j++) {
            int col0 = colBase + j * 8 + (lane & 3) * 2;
            float b0 = __ldg(&bias[col0]), b1 = __ldg(&bias[col0 + 1]);
            #pragma unroll
            for (int half = 0; half < 2; half++) {
                int row = row0 + half * 8;
                float2 v = make_float2(sc[j][half * 2 + 0] + b0, sc[j][half * 2 + 1] + b1);
                *(float2*)&out[(size_t)row * 256 + col0] = v;
            }
        }
    } else {
        // mode 2: V — split + smem transpose + store [bh][d][n]
        __syncthreads();
        __nv_bfloat16* svh = (__nv_bfloat16*)sm;           // [64][66]
        __nv_bfloat16* svl = svh + 64 * 66;
        #pragma unroll
        for (int j = 0; j < 8; j++) {
            int c0 = j * 8 + (lane & 3) * 2;
            float b0 = __ldg(&bias[colBase + c0]), b1 = __ldg(&bias[colBase + c0 + 1]);
            #pragma unroll
            for (int half = 0; half < 2; half++) {
                int mrow = wid * 16 + (lane >> 2) + half * 8;
                float v0 = sc[j][half * 2 + 0] + b0;
                float v1 = sc[j][half * 2 + 1] + b1;
                __nv_bfloat16 h0 = __float2bfloat16(v0);
                __nv_bfloat16 h1 = __float2bfloat16(v1);
                svh[mrow * 66 + c0]     = h0;
                svh[mrow * 66 + c0 + 1] = h1;
                svl[mrow * 66 + c0]     = __float2bfloat16(v0 - __bfloat162float(h0));
                svl[mrow * 66 + c0 + 1] = __float2bfloat16(v1 - __bfloat162float(h1));
            }
        }
        __syncthreads();
        // read phase: each thread handles one column d (0..63) and 32 tokens
        int d   = tid >> 1;               // 0..63
        int nch = (tid & 1) * 32;         // 0 or 32
        int colg = colBase + d;
        int h = colg >> 5, dd = colg & 31;
        int bb = rowBase >> 11;
        int nt = (rowBase & (Nx - 1)) + nch;
        uint32_t ph[16], pl[16];
        #pragma unroll
        for (int m = 0; m < 16; m++) {
            uint32_t a0 = *(const unsigned short*)&svh[(nch + 2 * m) * 66 + d];
            uint32_t a1 = *(const unsigned short*)&svh[(nch + 2 * m + 1) * 66 + d];
            ph[m] = a0 | (a1 << 16);
            uint32_t b0 = *(const unsigned short*)&svl[(nch + 2 * m) * 66 + d];
            uint32_t b1 = *(const unsigned short*)&svl[(nch + 2 * m + 1) * 66 + d];
            pl[m] = b0 | (b1 << 16);
        }
        size_t base = ((size_t)((bb * Hx + h) * HDx + dd)) * Nx + nt;
        #pragma unroll
        for (int q = 0; q < 4; q++) {
            *(uint4*)&g_Vthi[base + q * 8] = make_uint4(ph[q*4+0], ph[q*4+1], ph[q*4+2], ph[q*4+3]);
            *(uint4*)&g_Vtlo[base + q * 8] = make_uint4(pl[q*4+0], pl[q*4+1], pl[q*4+2], pl[q*4+3]);
        }
    }
}

// ---------------------------------------------------------------------------
// Attention kernel: mma.sync flash attention, cp.async double-buffered KV,
// fused per-kstep epilogue+PV, 3 CTAs/SM target.
// ---------------------------------------------------------------------------
// exp2-domain constants: p = exp2(s*topo*SCL2 - SM2)
#define SCL2 0.510091910551f   /* (2/sqrt(32)) * log2(e) */
#define SM2  16.4467223514f    /* 11.4 * log2(e) */

#define SQHI 0u
#define SQLO 8192u
#define BUF0 16384u
#define BUFSTRIDE 24576u
#define KHO 0u
#define KLO_ 8192u
#define VHO 16384u
#define VLO_ 20480u
#define ATTN_SMEM 65536u

__device__ __forceinline__ void issue_kv(uint32_t sb, uint32_t buf, int m0,
                                         const __nv_bfloat16* Kh, const __nv_bfloat16* Kl,
                                         const __nv_bfloat16* Vh, const __nv_bfloat16* Vl,
                                         int tid)
{
    #pragma unroll
    for (int i = 0; i < 4; i++) {
        int idx = tid + i * 128;
        int r = idx >> 3, seg = idx & 7;
        uint32_t so = sw128((uint32_t)(r * 128 + seg * 16));
        cp16(sb + buf + KHO  + so, Kh + (size_t)(m0 + r) * Fx + seg * 8);
        cp16(sb + buf + KLO_ + so, Kl + (size_t)(m0 + r) * Fx + seg * 8);
    }
    #pragma unroll
    for (int i = 0; i < 2; i++) {
        int idx = tid + i * 128;
        int d = idx >> 3, seg = idx & 7;
        uint32_t so = sw128((uint32_t)(d * 128 + seg * 16));
        cp16(sb + buf + VHO  + so, Vh + (size_t)d * Nx + m0 + seg * 8);
        cp16(sb + buf + VLO_ + so, Vl + (size_t)d * Nx + m0 + seg * 8);
    }
}

__global__ __launch_bounds__(128, 3)
void attn_kernel(const float* __restrict__ topo)
{
    extern __shared__ char sm[];
    const uint32_t sb = smem_u32(sm);

    const int tid  = threadIdx.x;
    const int wid  = tid >> 5;
    const int lane = tid & 31;
    const int n0 = blockIdx.x * 64;
    const int h  = blockIdx.y, b = blockIdx.z;
    const int bh = b * Hx + h;
    const int qr0 = wid * 16;

    const __nv_bfloat16* Qh = g_Qhi + ((size_t)bh * Nx + n0) * Fx;
    const __nv_bfloat16* Ql = g_Qlo + ((size_t)bh * Nx + n0) * Fx;
    const __nv_bfloat16* Kh = g_Khi + (size_t)bh * Nx * Fx;
    const __nv_bfloat16* Kl = g_Klo + (size_t)bh * Nx * Fx;
    const __nv_bfloat16* Vh = g_Vthi + (size_t)bh * HDx * Nx;
    const __nv_bfloat16* Vl = g_Vtlo + (size_t)bh * HDx * Nx;

    // Q tile -> smem
    #pragma unroll
    for (int i = 0; i < 4; i++) {
        int idx = tid + i * 128;
        int r = idx >> 3, seg = idx & 7;
        uint32_t so = sw128((uint32_t)(r * 128 + seg * 16));
        *(float4*)(sm + SQHI + so) = *(const float4*)(Qh + (size_t)r * Fx + seg * 8);
        *(float4*)(sm + SQLO + so) = *(const float4*)(Ql + (size_t)r * Fx + seg * 8);
    }
    // prologue: prefetch KV tile 0
    issue_kv(sb, BUF0, 0, Kh, Kl, Vh, Vl, tid);
    CP_COMMIT();
    __syncthreads();

    // Q fragments
    uint32_t aQh[4][4], aQl[4][4];
    {
        int qrow = qr0 + (lane & 15);
        int colp = (lane >> 4) * 16;
        #pragma unroll
        for (int ks = 0; ks < 4; ks++) {
            uint32_t off = sw128((uint32_t)(qrow * 128 + ks * 32 + colp));
            ldsm4(aQh[ks], sb + SQHI + off);
            ldsm4(aQl[ks], sb + SQLO + off);
        }
    }

    const int bnrow = (lane & 7) + ((lane >> 4) << 3);
    const int bkcol = ((lane >> 3) & 1) * 16;

    float oc[4][4] = {};
    float lsum0 = 0.f, lsum1 = 0.f;

    const int trow = n0 + qr0 + (lane >> 2);
    const float* topoB = topo + ((size_t)b * Nx + trow) * Nx + (lane & 3) * 2;

    for (int t = 0; t < Nx / 64; t++) {
        const int m0 = t * 64;
        const uint32_t buf = BUF0 + (uint32_t)(t & 1) * BUFSTRIDE;

        if (t + 1 < Nx / 64) {
            issue_kv(sb, BUF0 + (uint32_t)((t + 1) & 1) * BUFSTRIDE, m0 + 64,
                     Kh, Kl, Vh, Vl, tid);
            CP_COMMIT();
            asm volatile("cp.async.wait_group 1;" ::: "memory");
        } else {
            asm volatile("cp.async.wait_group 0;" ::: "memory");
        }
        __syncthreads();

        // topo loads straight into fragment lanes (hidden behind S-MMA)
        float2 tp0[8], tp1[8];
        {
            const float* p0 = topoB + m0;
            #pragma unroll
            for (int j = 0; j < 8; j++) {
                tp0[j] = *(const float2*)(p0 + j * 8);
                tp1[j] = *(const float2*)(p0 + 8 * Nx + j * 8);
            }
        }

        // ---- S = Qf . Kf^T (3-way split), per-p K fragments (low reg) ----
        float scr[8][4] = {};
        #pragma unroll
        for (int ks = 0; ks < 4; ks++) {
            #pragma unroll
            for (int p = 0; p < 4; p++) {
                uint32_t kb[4], kbl[4];
                uint32_t off = sw128((uint32_t)((p * 16 + bnrow) * 128 + ks * 32 + bkcol));
                ldsm4(kb,  sb + buf + KHO  + off);
                ldsm4(kbl, sb + buf + KLO_ + off);
                mma_bf16(scr[2*p],   aQh[ks], &kb[0]);
                mma_bf16(scr[2*p+1], aQh[ks], &kb[2]);
                mma_bf16(scr[2*p],   aQh[ks], &kbl[0]);
                mma_bf16(scr[2*p+1], aQh[ks], &kbl[2]);
                mma_bf16(scr[2*p],   aQl[ks], &kb[0]);
                mma_bf16(scr[2*p+1], aQl[ks], &kb[2]);
            }
        }

        // ---- fused epilogue + PV, per kstep (interleaves MUFU with HMMA) ----
        #pragma unroll
        for (int ks = 0; ks < 4; ks++) {
            uint32_t pAh[4], pAl[4];
            #pragma unroll
            for (int jj = 0; jj < 2; jj++) {
                const int j = 2 * ks + jj;
                float p00 = exp2f(fmaf(scr[j][0] * tp0[j].x, SCL2, -SM2));
                float p01 = exp2f(fmaf(scr[j][1] * tp0[j].y, SCL2, -SM2));
                float p10 = exp2f(fmaf(scr[j][2] * tp1[j].x, SCL2, -SM2));
                float p11 = exp2f(fmaf(scr[j][3] * tp1[j].y, SCL2, -SM2));
                lsum0 += p00 + p01;
                lsum1 += p10 + p11;
                uint32_t h0, l0, h1, l1;
                split2(p00, p01, h0, l0);
                split2(p10, p11, h1, l1);
                pAh[jj*2 + 0] = h0;  pAh[jj*2 + 1] = h1;
                pAl[jj*2 + 0] = l0;  pAl[jj*2 + 1] = l1;
            }
            uint32_t vb[8], vbl[8];
            #pragma unroll
            for (int p = 0; p < 2; p++) {
                uint32_t off = sw128((uint32_t)((p * 16 + bnrow) * 128 + ks * 32 + bkcol));
                ldsm4(&vb[p * 4],  sb + buf + VHO  + off);
                ldsm4(&vbl[p * 4], sb + buf + VLO_ + off);
            }
            #pragma unroll
            for (int jd = 0; jd < 4; jd++) mma_bf16(oc[jd], pAh, &vb[jd * 2]);
            #pragma unroll
            for (int jd = 0; jd < 4; jd++) mma_bf16(oc[jd], pAl, &vb[jd * 2]);
            #pragma unroll
            for (int jd = 0; jd < 4; jd++) mma_bf16(oc[jd], pAh, &vbl[jd * 2]);
        }
        __syncthreads();
    }

    // finalize: reduce l over the quad, normalize, split-store O
    lsum0 += __shfl_xor_sync(0xffffffffu, lsum0, 1);
    lsum0 += __shfl_xor_sync(0xffffffffu, lsum0, 2);
    lsum1 += __shfl_xor_sync(0xffffffffu, lsum1, 1);
    lsum1 += __shfl_xor_sync(0xffffffffu, lsum1, 2);
    const float inv0 = 1.0f / lsum0;
    const float inv1 = 1.0f / lsum1;

    const int r0 = n0 + qr0 + (lane >> 2);
    size_t base0 = ((size_t)(b * Nx + r0)) * DIMx + h * HDx + (lane & 3) * 2;
    size_t base1 = base0 + 8 * DIMx;
    #pragma unroll
    for (int jd = 0; jd < 4; jd++) {
        uint32_t hp, lp;
        split2(oc[jd][0] * inv0, oc[jd][1] * inv0, hp, lp);
        *(uint32_t*)&g_AOh[base0 + jd * 8] = hp;
        *(uint32_t*)&g_AOl[base0 + jd * 8] = lp;
        split2(oc[jd][2] * inv1, oc[jd][3] * inv1, hp, lp);
        *(uint32_t*)&g_AOh[base1 + jd * 8] = hp;
        *(uint32_t*)&g_AOl[base1 + jd * 8] = lp;
    }
}

// ---------------------------------------------------------------------------
extern "C" void kernel_launch(void* const* d_in, const int* in_sizes, int n_in,
                              void* d_out, int out_size)
{
    const float* x    = (const float*)d_in[0];
    const float* topo = (const float*)d_in[1];
    const float* Wq   = (const float*)d_in[2];
    const float* bq   = (const float*)d_in[3];
    const float* Wk   = (const float*)d_in[4];
    const float* bk   = (const float*)d_in[5];
    const float* Wv   = (const float*)d_in[6];
    const float* bv   = (const float*)d_in[7];
    const float* Wo   = (const float*)d_in[8];
    const float* bo   = (const float*)d_in[9];
    float* out = (float*)d_out;
    (void)in_sizes; (void)n_in; (void)out_size;

    cudaFuncSetAttribute(attn_kernel,
                         cudaFuncAttributeMaxDynamicSharedMemorySize, ATTN_SMEM);

    split_x_kernel<<<2048, 256>>>(x);
    split_w_kernel<<<1024, 256>>>(Wq, Wk, Wv, Wo);

    dim3 gq(4, 128, 3);
    gemm_kernel<<<gq, 128>>>(0, bq, bk, bv, bo, out);

    dim3 ga(Nx / 64, Hx, Bx);
    attn_kernel<<<ga, 128, ATTN_SMEM>>>(topo);

    dim3 go(4, 128, 1);
    gemm_kernel<<<go, 128>>>(3, bq, bk, bv, bo, out);
}